// round 9
// baseline (speedup 1.0000x reference)
#include <cuda_runtime.h>
#include <cstdint>

// RWKV v4 single-token forward, persistent kernel, round 9.
// R8 (TMA-streamed weights) with the pipeline fixed: ring of 6 x 32KB smem
// tile buffers (6 TMA loads outstanding per SM vs 2), ring state persists
// across stages/layers, next-stage tiles issued before each grid barrier.
// Rationale: LDG path is issue-floor-capped at ~2.4TB/s (all R2-R7 kernels
// plateaued there); TMA bypasses the LSU and reaches the LTS cap if enough
// requests are in flight. R8 failed only on pipeline depth (2 bufs = 25% duty).

#define E    1024
#define HH   4096
#define NL   24
#define NV   50277
#define T    1024
#define WPB  32
#define TILE_R 8
#define TILE_F (TILE_R * E)
#define NBUF 6

// ---- persistent device scratch ----
__device__ float g_kvr[3 * E];
__device__ float g_ow[E];
__device__ float g_fk[HH];
__device__ float g_fr[E];
__device__ __align__(16) float g_fvd[4 * E];   // [row*4 + c] quarter partials
__device__ unsigned int g_bar[2];              // memset per launch

struct P {
    const float *ctx, *state, *ln0w, *ln0b, *ln1w, *ln1b, *ln2w, *ln2b;
    const float *td, *tf, *tmk, *tmv, *tmr, *kw, *vw, *rw, *ow;
    const float *ftmk, *ftmr, *fkw, *frw, *fvw, *lnoutw, *lnoutb, *head;
    float* out;
    int nb;
    int ws;
};

__device__ __forceinline__ void grid_sync(int nb) {
    __syncthreads();
    if (threadIdx.x == 0) {
        unsigned int gen = ((volatile unsigned int*)g_bar)[1];
        __threadfence();
        if (atomicAdd(&g_bar[0], 1u) == (unsigned int)(nb - 1)) {
            atomicExch(&g_bar[0], 0u);
            __threadfence();
            atomicAdd(&g_bar[1], 1u);
        } else {
            while (((volatile unsigned int*)g_bar)[1] == gen) { __nanosleep(64); }
        }
        __threadfence();
    }
    __syncthreads();
}

__device__ __forceinline__ void block_reduce2(float& a, float& b, float* sr) {
    #pragma unroll
    for (int o = 16; o; o >>= 1) {
        a += __shfl_down_sync(0xFFFFFFFFu, a, o);
        b += __shfl_down_sync(0xFFFFFFFFu, b, o);
    }
    int w = threadIdx.x >> 5, l = threadIdx.x & 31;
    __syncthreads();
    if (l == 0) { sr[w] = a; sr[w + WPB] = b; }
    __syncthreads();
    if (threadIdx.x == 0) {
        float sa = 0.f, sb2 = 0.f;
        #pragma unroll
        for (int i = 0; i < WPB; i++) { sa += sr[i]; sb2 += sr[i + WPB]; }
        sr[2 * WPB] = sa; sr[2 * WPB + 1] = sb2;
    }
    __syncthreads();
    a = sr[2 * WPB];
    b = sr[2 * WPB + 1];
}

// ---- mbarrier / bulk-copy primitives ----
__device__ __forceinline__ void mb_init(uint32_t a, uint32_t cnt) {
    asm volatile("mbarrier.init.shared.b64 [%0], %1;" :: "r"(a), "r"(cnt) : "memory");
}
__device__ __forceinline__ void mb_expect(uint32_t a, uint32_t tx) {
    asm volatile("mbarrier.arrive.expect_tx.shared.b64 _, [%0], %1;" :: "r"(a), "r"(tx) : "memory");
}
__device__ __forceinline__ void mb_wait(uint32_t a, uint32_t parity) {
    uint32_t done;
    asm volatile(
        "{\n\t.reg .pred p;\n\t"
        "mbarrier.try_wait.parity.acquire.cta.shared::cta.b64 p, [%1], %2;\n\t"
        "selp.b32 %0, 1, 0, p;\n\t}"
        : "=r"(done) : "r"(a), "r"(parity) : "memory");
    if (!done) {
        asm volatile(
            "{\n\t.reg .pred P1;\n\t"
            "WAIT_LOOP_%=:\n\t"
            "mbarrier.try_wait.parity.acquire.cta.shared::cta.b64 P1, [%0], %1, 0x989680;\n\t"
            "@P1 bra.uni WAIT_DONE_%=;\n\t"
            "bra.uni WAIT_LOOP_%=;\n\t"
            "WAIT_DONE_%=:\n\t}"
            :: "r"(a), "r"(parity) : "memory");
    }
}
__device__ __forceinline__ void bulk_ld(uint32_t dst, const float* src, uint32_t bytes, uint32_t mbar) {
    asm volatile(
        "cp.async.bulk.shared::cluster.global.mbarrier::complete_tx::bytes [%0], [%1], %2, [%3];"
        :: "r"(dst), "l"(src), "r"(bytes), "r"(mbar) : "memory");
}

// ---- virtual-row mapping (all stages: 4KB contiguous rows) ----
__device__ __forceinline__ const float* srcptr(const P& p, int stg, int l, int vr) {
    switch (stg) {
        case 0: { int m = vr >> 10;
                  const float* W = (m == 0 ? p.kw : (m == 1 ? p.vw : p.rw)) + (size_t)l * E * E;
                  return W + (size_t)(vr & 1023) * E; }
        case 1: return p.ow + (size_t)l * E * E + (size_t)vr * E;
        case 2: return (vr < 4096) ? p.fkw + (size_t)l * HH * E + (size_t)vr * E
                                   : p.frw + (size_t)l * E * E + (size_t)(vr - 4096) * E;
        case 3: return p.fvw + (size_t)l * E * HH + (size_t)vr * E;
        default: return p.head + (size_t)vr * E;
    }
}
__device__ __forceinline__ int capf(int stg, int vr) {
    if (stg == 0) return 1024 - (vr & 1023);
    if (stg == 2) return (vr < 4096) ? (4096 - vr) : (5120 - vr);
    return 1 << 30;
}
__device__ __forceinline__ int xoff(int stg, int vr) {
    switch (stg) {
        case 0: return (vr >> 10) << 10;
        case 2: return (vr < 4096) ? 0 : E;
        case 3: return (vr & 3) << 10;
        default: return 0;
    }
}
__device__ __forceinline__ float* outp(const P& p, int stg, int vr) {
    switch (stg) {
        case 0: return g_kvr + vr;
        case 1: return g_ow + vr;
        case 2: return (vr < 4096) ? g_fk + vr : g_fr + (vr - 4096);
        case 3: return g_fvd + vr;
        default: return p.out + vr;
    }
}

// ---- persistent ring pipeline over NBUF tile buffers ----
struct Ring {
    int icur, iend, stg, l;
    int isl, csl, outst;
    int ivr[NBUF], inr[NBUF], ph[NBUF];
};

__device__ __forceinline__ void ring_issue(Ring& q, const P& p,
                                           uint32_t tiles_u32, uint32_t mb) {
    if (q.icur >= q.iend || q.outst >= NBUF) return;
    int nr = q.iend - q.icur;
    if (nr > TILE_R) nr = TILE_R;
    int c = capf(q.stg, q.icur);
    if (nr > c) nr = c;
    int s = q.isl;
    q.ivr[s] = q.icur; q.inr[s] = nr;
    if (threadIdx.x == 0) {
        uint32_t bytes = (uint32_t)nr * E * 4u;
        mb_expect(mb + s * 8, bytes);
        bulk_ld(tiles_u32 + (uint32_t)s * TILE_F * 4u, srcptr(p, q.stg, q.l, q.icur), bytes, mb + s * 8);
    }
    q.icur += nr;
    q.isl = (q.isl + 1) % NBUF;
    q.outst++;
}

__device__ __forceinline__ void ring_begin(Ring& q, int stg, int l, int NVR, const P& p,
                                           uint32_t tiles_u32, uint32_t mb) {
    q.stg = stg; q.l = l;
    q.icur = (int)(((long long)NVR * blockIdx.x) / p.nb);
    q.iend = (int)(((long long)NVR * (blockIdx.x + 1)) / p.nb);
    #pragma unroll
    for (int i = 0; i < NBUF; i++) ring_issue(q, p, tiles_u32, mb);
}

__device__ __forceinline__ void ring_drain(Ring& q, const P& p, float* tiles_f, float* sop,
                                           float (*spart)[32], uint32_t tiles_u32, uint32_t mb) {
    const int tid = threadIdx.x, lane = tid & 31, w = tid >> 5;
    while (q.outst > 0) {
        int s = q.csl;
        mb_wait(mb + s * 8, (uint32_t)q.ph[s]);
        q.ph[s] ^= 1;
        int nr = q.inr[s], tvr = q.ivr[s];
        int r = w >> 2, qd = w & 3;
        if (r < nr) {
            const float4* wv = (const float4*)(tiles_f + s * TILE_F + r * E + qd * 256);
            const float4* xv = (const float4*)(sop + xoff(q.stg, tvr + r) + qd * 256);
            float4 w0 = wv[lane],      x0 = xv[lane];
            float4 w1 = wv[lane + 32], x1 = xv[lane + 32];
            float acc = w0.x * x0.x + w0.y * x0.y + w0.z * x0.z + w0.w * x0.w
                      + w1.x * x1.x + w1.y * x1.y + w1.z * x1.z + w1.w * x1.w;
            #pragma unroll
            for (int o = 16; o; o >>= 1) acc += __shfl_down_sync(0xFFFFFFFFu, acc, o);
            if (lane == 0) spart[s][w] = acc;
        }
        __syncthreads();                      // buffer s fully read; safe to reuse
        q.outst--;
        q.csl = (q.csl + 1) % NBUF;
        ring_issue(q, p, tiles_u32, mb);      // refill freed slot
        if (tid < nr) {
            float4 v = ((const float4*)spart[s])[tid];
            *outp(p, q.stg, tvr + tid) = (v.x + v.y) + (v.z + v.w);
        }
    }
}

#define SMEM_FLOATS (E + HH + NBUF * TILE_F)

__global__ void __launch_bounds__(T, 1) rwkv_kernel(P p) {
    extern __shared__ float smem[];
    float* sx      = smem;             // [E]
    float* sop     = smem + E;         // [HH]
    float* tiles_f = smem + E + HH;    // [NBUF * TILE_F]
    __shared__ float sred[2 * WPB + 2];
    __shared__ __align__(16) float spart[NBUF][32];
    __shared__ __align__(8) uint64_t mbars[NBUF];

    const int tid = threadIdx.x;
    const bool w0 = (p.ws && blockIdx.x == 0);
    float* outS = p.out + NV;

    uint32_t mb, tiles_u32;
    asm("{ .reg .u64 t; cvta.to.shared.u64 t, %1; cvt.u32.u64 %0, t; }"
        : "=r"(mb) : "l"((void*)&mbars[0]));
    asm("{ .reg .u64 t; cvta.to.shared.u64 t, %1; cvt.u32.u64 %0, t; }"
        : "=r"(tiles_u32) : "l"((void*)tiles_f));

    if (tid == 0)
        for (int i = 0; i < NBUF; i++) mb_init(mb + i * 8, 1);
    __syncthreads();

    Ring q;
    q.isl = 0; q.csl = 0; q.outst = 0;
    #pragma unroll
    for (int i = 0; i < NBUF; i++) q.ph[i] = 0;

    // issue layer-0 kvr tiles; LN0 runs under the TMA
    ring_begin(q, 0, 0, 3 * E, p, tiles_u32, mb);

    float s = 0.f, s2 = 0.f;
    for (int i = tid; i < E; i += T) { float v = __ldg(p.ctx + i); sx[i] = v; s += v; s2 += v * v; }
    block_reduce2(s, s2, sred);
    {
        float mu = s * (1.f / E);
        float rs = rsqrtf(s2 * (1.f / E) - mu * mu + 1e-5f);
        for (int i = tid; i < E; i += T)
            sx[i] = (sx[i] - mu) * rs * __ldg(p.ln0w + i) + __ldg(p.ln0b + i);
    }
    __syncthreads();

    for (int l = 0; l < NL; l++) {
        const float* st = p.state + (size_t)l * 5 * E;

        // ---- elementwise A: combine prev FFN + LN1 + time-mix ----
        if (l > 0) {
            for (int i = tid; i < E; i += T) {
                float4 fv4 = *(const float4*)(g_fvd + 4 * i);
                float fr = 1.f / (1.f + __expf(-g_fr[i]));
                sx[i] += fr * ((fv4.x + fv4.y) + (fv4.z + fv4.w));
            }
        }
        s = 0.f; s2 = 0.f;
        for (int i = tid; i < E; i += T) { float v = sx[i]; s += v; s2 += v * v; }
        block_reduce2(s, s2, sred);
        {
            float mu = s * (1.f / E);
            float rs = rsqrtf(s2 * (1.f / E) - mu * mu + 1e-5f);
            for (int i = tid; i < E; i += T) {
                float xn = (sx[i] - mu) * rs * __ldg(p.ln1w + l * E + i) + __ldg(p.ln1b + l * E + i);
                float spv = __ldg(st + E + i);
                float a = __ldg(p.tmk + l * E + i), b = __ldg(p.tmv + l * E + i), c = __ldg(p.tmr + l * E + i);
                sop[i]         = xn * a + spv * (1.f - a);
                sop[E + i]     = xn * b + spv * (1.f - b);
                sop[2 * E + i] = xn * c + spv * (1.f - c);
                if (w0) outS[(size_t)(5 * l + 1) * E + i] = xn;
            }
        }
        __syncthreads();
        ring_drain(q, p, tiles_f, sop, spart, tiles_u32, mb);   // -> g_kvr
        ring_begin(q, 1, l, E, p, tiles_u32, mb);               // issue ow
        grid_sync(p.nb);

        // ---- elementwise B: WKV ----
        for (int i = tid; i < E; i += T) {
            float k  = g_kvr[i];
            float v  = g_kvr[E + i];
            float rr = g_kvr[2 * E + i];
            float A = __ldg(st + 2 * E + i), B = __ldg(st + 3 * E + i), Pp = __ldg(st + 4 * E + i);
            float ww = __ldg(p.tf + l * E + i) + k;
            float qq = fmaxf(Pp, ww);
            float e1 = __expf(Pp - qq), e2 = __expf(ww - qq);
            float num = e1 * A + e2 * v, den = e1 * B + e2;
            float r = 1.f / (1.f + __expf(-rr));
            sop[i] = r * num / den;
            if (w0) {
                float ww2 = Pp + __ldg(p.td + l * E + i);
                float p2 = fmaxf(ww2, k);
                float e1b = __expf(ww2 - p2), e2b = __expf(k - p2);
                outS[(size_t)(5 * l + 2) * E + i] = e1b * A + e2b * v;
                outS[(size_t)(5 * l + 3) * E + i] = e1b * B + e2b;
                outS[(size_t)(5 * l + 4) * E + i] = p2;
            }
        }
        __syncthreads();
        ring_drain(q, p, tiles_f, sop, spart, tiles_u32, mb);   // -> g_ow
        ring_begin(q, 2, l, HH + E, p, tiles_u32, mb);          // issue fk+fr
        grid_sync(p.nb);

        // ---- elementwise C: x += ow; LN2 + chan-mix ----
        for (int i = tid; i < E; i += T) sx[i] += g_ow[i];
        s = 0.f; s2 = 0.f;
        for (int i = tid; i < E; i += T) { float v = sx[i]; s += v; s2 += v * v; }
        block_reduce2(s, s2, sred);
        {
            float mu = s * (1.f / E);
            float rs = rsqrtf(s2 * (1.f / E) - mu * mu + 1e-5f);
            for (int i = tid; i < E; i += T) {
                float xn2 = (sx[i] - mu) * rs * __ldg(p.ln2w + l * E + i) + __ldg(p.ln2b + l * E + i);
                float sv = __ldg(st + i);
                float a = __ldg(p.ftmk + l * E + i), b = __ldg(p.ftmr + l * E + i);
                sop[i]     = xn2 * a + sv * (1.f - a);
                sop[E + i] = xn2 * b + sv * (1.f - b);
                if (w0) outS[(size_t)(5 * l + 0) * E + i] = xn2;
            }
        }
        __syncthreads();
        ring_drain(q, p, tiles_f, sop, spart, tiles_u32, mb);   // -> g_fk, g_fr
        ring_begin(q, 3, l, 4 * E, p, tiles_u32, mb);           // issue fv
        grid_sync(p.nb);

        // ---- elementwise D: kk = relu^2(fk) ----
        for (int i = tid; i < HH; i += T) {
            float a = fmaxf(g_fk[i], 0.f);
            sop[i] = a * a;
        }
        __syncthreads();
        ring_drain(q, p, tiles_f, sop, spart, tiles_u32, mb);   // -> g_fvd
        if (l + 1 < NL) ring_begin(q, 0, l + 1, 3 * E, p, tiles_u32, mb);
        else            ring_begin(q, 4, 0, NV, p, tiles_u32, mb);  // issue head
        grid_sync(p.nb);
    }

    // ---- final: combine last FFN, LN_out, head GEMV ----
    for (int i = tid; i < E; i += T) {
        float4 fv4 = *(const float4*)(g_fvd + 4 * i);
        float fr = 1.f / (1.f + __expf(-g_fr[i]));
        sx[i] += fr * ((fv4.x + fv4.y) + (fv4.z + fv4.w));
    }
    s = 0.f; s2 = 0.f;
    for (int i = tid; i < E; i += T) { float v = sx[i]; s += v; s2 += v * v; }
    block_reduce2(s, s2, sred);
    {
        float mu = s * (1.f / E);
        float rs = rsqrtf(s2 * (1.f / E) - mu * mu + 1e-5f);
        for (int i = tid; i < E; i += T)
            sop[i] = (sx[i] - mu) * rs * __ldg(p.lnoutw + i) + __ldg(p.lnoutb + i);
    }
    __syncthreads();
    ring_drain(q, p, tiles_f, sop, spart, tiles_u32, mb);       // -> p.out[0..NV)
}

extern "C" void kernel_launch(void* const* d_in, const int* in_sizes, int n_in,
                              void* d_out, int out_size) {
    (void)in_sizes; (void)n_in;
    P p;
    p.ctx    = (const float*)d_in[0];
    p.state  = (const float*)d_in[1];
    p.ln0w   = (const float*)d_in[2];
    p.ln0b   = (const float*)d_in[3];
    p.ln1w   = (const float*)d_in[4];
    p.ln1b   = (const float*)d_in[5];
    p.ln2w   = (const float*)d_in[6];
    p.ln2b   = (const float*)d_in[7];
    p.td     = (const float*)d_in[8];
    p.tf     = (const float*)d_in[9];
    p.tmk    = (const float*)d_in[10];
    p.tmv    = (const float*)d_in[11];
    p.tmr    = (const float*)d_in[12];
    p.kw     = (const float*)d_in[13];
    p.vw     = (const float*)d_in[14];
    p.rw     = (const float*)d_in[15];
    p.ow     = (const float*)d_in[16];
    p.ftmk   = (const float*)d_in[17];
    p.ftmr   = (const float*)d_in[18];
    p.fkw    = (const float*)d_in[19];
    p.frw    = (const float*)d_in[20];
    p.fvw    = (const float*)d_in[21];
    p.lnoutw = (const float*)d_in[22];
    p.lnoutb = (const float*)d_in[23];
    p.head   = (const float*)d_in[24];
    p.out    = (float*)d_out;

    int dev = 0;
    cudaGetDevice(&dev);
    int nsm = 0;
    cudaDeviceGetAttribute(&nsm, cudaDevAttrMultiProcessorCount, dev);
    if (nsm <= 0) nsm = 148;
    if (nsm > 256) nsm = 256;
    p.nb = nsm;
    p.ws = (out_size >= NV + 5 * NL * E) ? 1 : 0;

    cudaFuncSetAttribute(rwkv_kernel, cudaFuncAttributeMaxDynamicSharedMemorySize,
                         SMEM_FLOATS * sizeof(float));

    void* baddr = nullptr;
    cudaGetSymbolAddress(&baddr, g_bar);
    cudaMemsetAsync(baddr, 0, sizeof(unsigned int) * 2, 0);

    rwkv_kernel<<<nsm, T, SMEM_FLOATS * sizeof(float)>>>(p);
}

// round 10
// speedup vs baseline: 1.5554x; 1.5554x over previous
#include <cuda_runtime.h>
#include <cstdint>

// RWKV v4 single-token forward, persistent kernel, round 10.
// HYBRID weight streaming: every warp alternates GEMV rows between (a) direct
// LDG.128 dots (capped chip-wide at ~2.4TB/s by the per-SM LDG issue floor)
// and (b) a private 4KB smem slot filled by cp.async.bulk with a PRIVATE
// per-warp mbarrier (no block-wide sync in the consume path -- the flaw that
// killed R8/R9). The two delivery engines run concurrently and add.
// TMA for row t+NW is issued before barriers / previous dots so its latency
// hides under LDG work. Worst case TMA underdelivers -> degrades to ~R5.

#define E    1024
#define HH   4096
#define NL   24
#define NV   50277
#define T    1024
#define WPB  32

// ---- persistent device scratch ----
__device__ float g_kvr[3 * E];
__device__ float g_ow[E];
__device__ float g_fk[HH];
__device__ float g_fr[E];
__device__ __align__(16) float g_fvd[4 * E];   // [row*4 + c] quarter partials
__device__ unsigned int g_bar[2];              // memset per launch

struct P {
    const float *ctx, *state, *ln0w, *ln0b, *ln1w, *ln1b, *ln2w, *ln2b;
    const float *td, *tf, *tmk, *tmv, *tmr, *kw, *vw, *rw, *ow;
    const float *ftmk, *ftmr, *fkw, *frw, *fvw, *lnoutw, *lnoutb, *head;
    float* out;
    int nb;
    int ws;
};

__device__ __forceinline__ void grid_sync(int nb) {
    __syncthreads();
    if (threadIdx.x == 0) {
        unsigned int gen = ((volatile unsigned int*)g_bar)[1];
        __threadfence();
        if (atomicAdd(&g_bar[0], 1u) == (unsigned int)(nb - 1)) {
            atomicExch(&g_bar[0], 0u);
            __threadfence();
            atomicAdd(&g_bar[1], 1u);
        } else {
            while (((volatile unsigned int*)g_bar)[1] == gen) { __nanosleep(64); }
        }
        __threadfence();
    }
    __syncthreads();
}

__device__ __forceinline__ void block_reduce2(float& a, float& b, float* sr) {
    #pragma unroll
    for (int o = 16; o; o >>= 1) {
        a += __shfl_down_sync(0xFFFFFFFFu, a, o);
        b += __shfl_down_sync(0xFFFFFFFFu, b, o);
    }
    int w = threadIdx.x >> 5, l = threadIdx.x & 31;
    __syncthreads();
    if (l == 0) { sr[w] = a; sr[w + WPB] = b; }
    __syncthreads();
    if (threadIdx.x == 0) {
        float sa = 0.f, sb2 = 0.f;
        #pragma unroll
        for (int i = 0; i < WPB; i++) { sa += sr[i]; sb2 += sr[i + WPB]; }
        sr[2 * WPB] = sa; sr[2 * WPB + 1] = sb2;
    }
    __syncthreads();
    a = sr[2 * WPB];
    b = sr[2 * WPB + 1];
}

// direct-global warp dot over 1024 floats (.cs = read-once)
__device__ __forceinline__ float dot_g(const float* __restrict__ w,
                                       const float* x, int lane) {
    const float4* __restrict__ w4 = (const float4*)w;
    const float4* x4 = (const float4*)x;
    float a0 = 0.f, a1 = 0.f, a2 = 0.f, a3 = 0.f;
    #pragma unroll
    for (int u = 0; u < 8; u += 4) {
        float4 wa = __ldcs(&w4[lane + 32 * u]);       float4 xa = x4[lane + 32 * u];
        float4 wb = __ldcs(&w4[lane + 32 * (u + 1)]); float4 xb = x4[lane + 32 * (u + 1)];
        float4 wc = __ldcs(&w4[lane + 32 * (u + 2)]); float4 xc = x4[lane + 32 * (u + 2)];
        float4 wd = __ldcs(&w4[lane + 32 * (u + 3)]); float4 xd = x4[lane + 32 * (u + 3)];
        a0 += wa.x * xa.x + wa.y * xa.y + wa.z * xa.z + wa.w * xa.w;
        a1 += wb.x * xb.x + wb.y * xb.y + wb.z * xb.z + wb.w * xb.w;
        a2 += wc.x * xc.x + wc.y * xc.y + wc.z * xc.z + wc.w * xc.w;
        a3 += wd.x * xd.x + wd.y * xd.y + wd.z * xd.z + wd.w * xd.w;
    }
    float acc = (a0 + a1) + (a2 + a3);
    #pragma unroll
    for (int o = 16; o; o >>= 1) acc += __shfl_down_sync(0xFFFFFFFFu, acc, o);
    return acc;
}

// smem-slot warp dot over 1024 floats
__device__ __forceinline__ float dot_s(const float* w, const float* x, int lane) {
    const float4* w4 = (const float4*)w;
    const float4* x4 = (const float4*)x;
    float a0 = 0.f, a1 = 0.f, a2 = 0.f, a3 = 0.f;
    #pragma unroll
    for (int u = 0; u < 8; u += 4) {
        float4 wa = w4[lane + 32 * u];       float4 xa = x4[lane + 32 * u];
        float4 wb = w4[lane + 32 * (u + 1)]; float4 xb = x4[lane + 32 * (u + 1)];
        float4 wc = w4[lane + 32 * (u + 2)]; float4 xc = x4[lane + 32 * (u + 2)];
        float4 wd = w4[lane + 32 * (u + 3)]; float4 xd = x4[lane + 32 * (u + 3)];
        a0 += wa.x * xa.x + wa.y * xa.y + wa.z * xa.z + wa.w * xa.w;
        a1 += wb.x * xb.x + wb.y * xb.y + wb.z * xb.z + wb.w * xb.w;
        a2 += wc.x * xc.x + wc.y * xc.y + wc.z * xc.z + wc.w * xc.w;
        a3 += wd.x * xd.x + wd.y * xd.y + wd.z * xd.z + wd.w * xd.w;
    }
    float acc = (a0 + a1) + (a2 + a3);
    #pragma unroll
    for (int o = 16; o; o >>= 1) acc += __shfl_down_sync(0xFFFFFFFFu, acc, o);
    return acc;
}

// ---- mbarrier / bulk-copy primitives ----
__device__ __forceinline__ void mb_init(uint32_t a, uint32_t cnt) {
    asm volatile("mbarrier.init.shared.b64 [%0], %1;" :: "r"(a), "r"(cnt) : "memory");
}
__device__ __forceinline__ void mb_expect(uint32_t a, uint32_t tx) {
    asm volatile("mbarrier.arrive.expect_tx.shared.b64 _, [%0], %1;" :: "r"(a), "r"(tx) : "memory");
}
__device__ __forceinline__ void mb_wait(uint32_t a, uint32_t parity) {
    uint32_t done;
    asm volatile(
        "{\n\t.reg .pred p;\n\t"
        "mbarrier.try_wait.parity.acquire.cta.shared::cta.b64 p, [%1], %2;\n\t"
        "selp.b32 %0, 1, 0, p;\n\t}"
        : "=r"(done) : "r"(a), "r"(parity) : "memory");
    if (!done) {
        asm volatile(
            "{\n\t.reg .pred P1;\n\t"
            "WAIT_LOOP_%=:\n\t"
            "mbarrier.try_wait.parity.acquire.cta.shared::cta.b64 P1, [%0], %1, 0x989680;\n\t"
            "@P1 bra.uni WAIT_DONE_%=;\n\t"
            "bra.uni WAIT_LOOP_%=;\n\t"
            "WAIT_DONE_%=:\n\t}"
            :: "r"(a), "r"(parity) : "memory");
    }
}
__device__ __forceinline__ void bulk_ld(uint32_t dst, const float* src, uint32_t bytes, uint32_t mbar) {
    asm volatile(
        "cp.async.bulk.shared::cluster.global.mbarrier::complete_tx::bytes [%0], [%1], %2, [%3];"
        :: "r"(dst), "l"(src), "r"(bytes), "r"(mbar) : "memory");
}

// ---- virtual-row mapping: every task is one 4KB row ----
__device__ __forceinline__ const float* srcptr(const P& p, int stg, int l, int vr) {
    switch (stg) {
        case 0: { int m = vr >> 10;
                  const float* W = (m == 0 ? p.kw : (m == 1 ? p.vw : p.rw)) + (size_t)l * E * E;
                  return W + (size_t)(vr & 1023) * E; }
        case 1: return p.ow + (size_t)l * E * E + (size_t)vr * E;
        case 2: return (vr < 4096) ? p.fkw + (size_t)l * HH * E + (size_t)vr * E
                                   : p.frw + (size_t)l * E * E + (size_t)(vr - 4096) * E;
        case 3: return p.fvw + (size_t)l * E * HH + (size_t)vr * E;
        default: return p.head + (size_t)vr * E;
    }
}
__device__ __forceinline__ int xoff(int stg, int vr) {
    switch (stg) {
        case 0: return (vr >> 10) << 10;
        case 2: return (vr < 4096) ? 0 : E;
        case 3: return (vr & 3) << 10;
        default: return 0;
    }
}
__device__ __forceinline__ float* outp(const P& p, int stg, int vr) {
    switch (stg) {
        case 0: return g_kvr + vr;
        case 1: return g_ow + vr;
        case 2: return (vr < 4096) ? g_fk + vr : g_fr + (vr - 4096);
        case 3: return g_fvd + vr;
        default: return p.out + vr;
    }
}

// pre-issue this warp's first TMA row (t = gw+NW) for a stage
__device__ __forceinline__ void issue_first(int stg, int l, int NT, const P& p,
                                            uint32_t slot_u32, uint32_t mybar,
                                            int lane, int gw, int NW) {
    int t1 = gw + NW;
    if (t1 < NT && lane == 0) {
        mb_expect(mybar, 4096u);
        bulk_ld(slot_u32, srcptr(p, stg, l, t1), 4096u, mybar);
    }
}

// interleaved LDG/TMA stage: even local rows via dot_g, odd via private slot
__device__ __forceinline__ void run_stage(int stg, int l, int NT, const P& p,
                                          float* sop, float* slot, uint32_t slot_u32,
                                          uint32_t mybar, int& ph,
                                          int lane, int gw, int NW) {
    int k = 0;
    for (int t = gw; t < NT; t += NW, k ^= 1) {
        float acc;
        if (k == 0) {
            acc = dot_g(srcptr(p, stg, l, t), sop + xoff(stg, t), lane);
        } else {
            mb_wait(mybar, (uint32_t)ph); ph ^= 1;
            acc = dot_s(slot, sop + xoff(stg, t), lane);
            int tn = t + 2 * NW;                 // next odd row for this warp
            if (tn < NT && lane == 0) {
                mb_expect(mybar, 4096u);
                bulk_ld(slot_u32, srcptr(p, stg, l, tn), 4096u, mybar);
            }
        }
        if (lane == 0) *outp(p, stg, t) = acc;
    }
}

#define SMEM_FLOATS (E + HH + WPB * E)

__global__ void __launch_bounds__(T, 1) rwkv_kernel(P p) {
    extern __shared__ float smem[];
    float* sx    = smem;               // [E]
    float* sop   = smem + E;           // [HH]
    float* slots = smem + E + HH;      // [WPB * E]  (4KB per warp)
    __shared__ float sred[2 * WPB + 2];
    __shared__ __align__(8) uint64_t mbars[WPB];

    const int tid = threadIdx.x, lane = tid & 31, warp = tid >> 5;
    const int gw = blockIdx.x * WPB + warp;
    const int NW = p.nb * WPB;
    const bool w0 = (p.ws && blockIdx.x == 0);
    float* outS = p.out + NV;

    float* slot = slots + warp * E;
    uint32_t mybar, slot_u32;
    asm("{ .reg .u64 t; cvta.to.shared.u64 t, %1; cvt.u32.u64 %0, t; }"
        : "=r"(mybar) : "l"((void*)&mbars[warp]));
    asm("{ .reg .u64 t; cvta.to.shared.u64 t, %1; cvt.u32.u64 %0, t; }"
        : "=r"(slot_u32) : "l"((void*)slot));

    if (lane == 0) mb_init(mybar, 1);
    __syncthreads();
    int ph = 0;

    // pre-issue layer-0 kvr TMA rows; LN0 runs under them
    issue_first(0, 0, 3 * E, p, slot_u32, mybar, lane, gw, NW);

    float s = 0.f, s2 = 0.f;
    for (int i = tid; i < E; i += T) { float v = __ldg(p.ctx + i); sx[i] = v; s += v; s2 += v * v; }
    block_reduce2(s, s2, sred);
    {
        float mu = s * (1.f / E);
        float rs = rsqrtf(s2 * (1.f / E) - mu * mu + 1e-5f);
        for (int i = tid; i < E; i += T)
            sx[i] = (sx[i] - mu) * rs * __ldg(p.ln0w + i) + __ldg(p.ln0b + i);
    }
    __syncthreads();

    for (int l = 0; l < NL; l++) {
        const float* st = p.state + (size_t)l * 5 * E;

        // ---- elementwise A: combine prev FFN + LN1 + time-mix ----
        if (l > 0) {
            for (int i = tid; i < E; i += T) {
                float4 fv4 = *(const float4*)(g_fvd + 4 * i);
                float fr = 1.f / (1.f + __expf(-g_fr[i]));
                sx[i] += fr * ((fv4.x + fv4.y) + (fv4.z + fv4.w));
            }
        }
        s = 0.f; s2 = 0.f;
        for (int i = tid; i < E; i += T) { float v = sx[i]; s += v; s2 += v * v; }
        block_reduce2(s, s2, sred);
        {
            float mu = s * (1.f / E);
            float rs = rsqrtf(s2 * (1.f / E) - mu * mu + 1e-5f);
            for (int i = tid; i < E; i += T) {
                float xn = (sx[i] - mu) * rs * __ldg(p.ln1w + l * E + i) + __ldg(p.ln1b + l * E + i);
                float spv = __ldg(st + E + i);
                float a = __ldg(p.tmk + l * E + i), b = __ldg(p.tmv + l * E + i), c = __ldg(p.tmr + l * E + i);
                sop[i]         = xn * a + spv * (1.f - a);
                sop[E + i]     = xn * b + spv * (1.f - b);
                sop[2 * E + i] = xn * c + spv * (1.f - c);
                if (w0) outS[(size_t)(5 * l + 1) * E + i] = xn;
            }
        }
        __syncthreads();
        run_stage(0, l, 3 * E, p, sop, slot, slot_u32, mybar, ph, lane, gw, NW);   // -> g_kvr
        issue_first(1, l, E, p, slot_u32, mybar, lane, gw, NW);
        grid_sync(p.nb);

        // ---- elementwise B: WKV ----
        for (int i = tid; i < E; i += T) {
            float k  = g_kvr[i];
            float v  = g_kvr[E + i];
            float rr = g_kvr[2 * E + i];
            float A = __ldg(st + 2 * E + i), B = __ldg(st + 3 * E + i), Pp = __ldg(st + 4 * E + i);
            float ww = __ldg(p.tf + l * E + i) + k;
            float qq = fmaxf(Pp, ww);
            float e1 = __expf(Pp - qq), e2 = __expf(ww - qq);
            float num = e1 * A + e2 * v, den = e1 * B + e2;
            float r = 1.f / (1.f + __expf(-rr));
            sop[i] = r * num / den;
            if (w0) {
                float ww2 = Pp + __ldg(p.td + l * E + i);
                float p2 = fmaxf(ww2, k);
                float e1b = __expf(ww2 - p2), e2b = __expf(k - p2);
                outS[(size_t)(5 * l + 2) * E + i] = e1b * A + e2b * v;
                outS[(size_t)(5 * l + 3) * E + i] = e1b * B + e2b;
                outS[(size_t)(5 * l + 4) * E + i] = p2;
            }
        }
        __syncthreads();
        run_stage(1, l, E, p, sop, slot, slot_u32, mybar, ph, lane, gw, NW);       // -> g_ow
        issue_first(2, l, HH + E, p, slot_u32, mybar, lane, gw, NW);
        grid_sync(p.nb);

        // ---- elementwise C: x += ow; LN2 + chan-mix ----
        for (int i = tid; i < E; i += T) sx[i] += g_ow[i];
        s = 0.f; s2 = 0.f;
        for (int i = tid; i < E; i += T) { float v = sx[i]; s += v; s2 += v * v; }
        block_reduce2(s, s2, sred);
        {
            float mu = s * (1.f / E);
            float rs = rsqrtf(s2 * (1.f / E) - mu * mu + 1e-5f);
            for (int i = tid; i < E; i += T) {
                float xn2 = (sx[i] - mu) * rs * __ldg(p.ln2w + l * E + i) + __ldg(p.ln2b + l * E + i);
                float sv = __ldg(st + i);
                float a = __ldg(p.ftmk + l * E + i), b = __ldg(p.ftmr + l * E + i);
                sop[i]     = xn2 * a + sv * (1.f - a);
                sop[E + i] = xn2 * b + sv * (1.f - b);
                if (w0) outS[(size_t)(5 * l + 0) * E + i] = xn2;
            }
        }
        __syncthreads();
        run_stage(2, l, HH + E, p, sop, slot, slot_u32, mybar, ph, lane, gw, NW);  // -> g_fk, g_fr
        issue_first(3, l, 4 * E, p, slot_u32, mybar, lane, gw, NW);
        grid_sync(p.nb);

        // ---- elementwise D: kk = relu^2(fk) ----
        for (int i = tid; i < HH; i += T) {
            float a = fmaxf(g_fk[i], 0.f);
            sop[i] = a * a;
        }
        __syncthreads();
        run_stage(3, l, 4 * E, p, sop, slot, slot_u32, mybar, ph, lane, gw, NW);   // -> g_fvd
        if (l + 1 < NL) issue_first(0, l + 1, 3 * E, p, slot_u32, mybar, lane, gw, NW);
        else            issue_first(4, 0, NV, p, slot_u32, mybar, lane, gw, NW);
        grid_sync(p.nb);
    }

    // ---- final: combine last FFN, LN_out, head GEMV ----
    for (int i = tid; i < E; i += T) {
        float4 fv4 = *(const float4*)(g_fvd + 4 * i);
        float fr = 1.f / (1.f + __expf(-g_fr[i]));
        sx[i] += fr * ((fv4.x + fv4.y) + (fv4.z + fv4.w));
    }
    s = 0.f; s2 = 0.f;
    for (int i = tid; i < E; i += T) { float v = sx[i]; s += v; s2 += v * v; }
    block_reduce2(s, s2, sred);
    {
        float mu = s * (1.f / E);
        float rs = rsqrtf(s2 * (1.f / E) - mu * mu + 1e-5f);
        for (int i = tid; i < E; i += T)
            sop[i] = (sx[i] - mu) * rs * __ldg(p.lnoutw + i) + __ldg(p.lnoutb + i);
    }
    __syncthreads();
    run_stage(4, 0, NV, p, sop, slot, slot_u32, mybar, ph, lane, gw, NW);          // -> logits
}

extern "C" void kernel_launch(void* const* d_in, const int* in_sizes, int n_in,
                              void* d_out, int out_size) {
    (void)in_sizes; (void)n_in;
    P p;
    p.ctx    = (const float*)d_in[0];
    p.state  = (const float*)d_in[1];
    p.ln0w   = (const float*)d_in[2];
    p.ln0b   = (const float*)d_in[3];
    p.ln1w   = (const float*)d_in[4];
    p.ln1b   = (const float*)d_in[5];
    p.ln2w   = (const float*)d_in[6];
    p.ln2b   = (const float*)d_in[7];
    p.td     = (const float*)d_in[8];
    p.tf     = (const float*)d_in[9];
    p.tmk    = (const float*)d_in[10];
    p.tmv    = (const float*)d_in[11];
    p.tmr    = (const float*)d_in[12];
    p.kw     = (const float*)d_in[13];
    p.vw     = (const float*)d_in[14];
    p.rw     = (const float*)d_in[15];
    p.ow     = (const float*)d_in[16];
    p.ftmk   = (const float*)d_in[17];
    p.ftmr   = (const float*)d_in[18];
    p.fkw    = (const float*)d_in[19];
    p.frw    = (const float*)d_in[20];
    p.fvw    = (const float*)d_in[21];
    p.lnoutw = (const float*)d_in[22];
    p.lnoutb = (const float*)d_in[23];
    p.head   = (const float*)d_in[24];
    p.out    = (float*)d_out;

    int dev = 0;
    cudaGetDevice(&dev);
    int nsm = 0;
    cudaDeviceGetAttribute(&nsm, cudaDevAttrMultiProcessorCount, dev);
    if (nsm <= 0) nsm = 148;
    if (nsm > 256) nsm = 256;
    p.nb = nsm;
    p.ws = (out_size >= NV + 5 * NL * E) ? 1 : 0;

    cudaFuncSetAttribute(rwkv_kernel, cudaFuncAttributeMaxDynamicSharedMemorySize,
                         SMEM_FLOATS * sizeof(float));

    void* baddr = nullptr;
    cudaGetSymbolAddress(&baddr, g_bar);
    cudaMemsetAsync(baddr, 0, sizeof(unsigned int) * 2, 0);

    rwkv_kernel<<<nsm, T, SMEM_FLOATS * sizeof(float)>>>(p);
}